// round 6
// baseline (speedup 1.0000x reference)
#include <cuda_runtime.h>
#include <math.h>
#include <stdint.h>

// ---------------- problem constants ----------------
#define B_      8
#define H_      128
#define W_      128
#define DIM_    256
#define HEADS_  16
#define DH_     16
#define HW_     (H_*W_)            // 16384
#define M_TOTAL (B_*HW_)           // 131072
#define N_QKV   (3*DIM_)           // 768
#define SLICES  8

// ---------------- scratch (no allocs -> __device__ globals) ----------------
__device__ float g_xt   [(size_t)M_TOTAL * DIM_];     // tf32-rounded x
__device__ float g_qkv  [(size_t)M_TOTAL * N_QKV];
__device__ float g_qkv2 [(size_t)M_TOTAL * N_QKV];    // v channels tf32-rounded
__device__ float g_part [SLICES * B_ * HEADS_ * DH_ * DH_];
__device__ float g_attn [B_ * HEADS_ * DH_ * DH_];
__device__ float g_wfT  [B_ * DIM_ * DIM_];           // tf32-rounded
__device__ float g_wqkvT[N_QKV * DIM_];               // tf32-rounded

// ---------------- helpers ----------------
__device__ __forceinline__ uint32_t smem_u32(const void* p) {
    uint32_t a;
    asm("{ .reg .u64 t; cvta.to.shared.u64 t, %1; cvt.u32.u64 %0, t; }" : "=r"(a) : "l"(p));
    return a;
}
__device__ __forceinline__ float f2tf32f(float f) {
    uint32_t r; asm("cvt.rna.tf32.f32 %0, %1;" : "=r"(r) : "f"(f));
    return __uint_as_float(r);
}
__device__ __forceinline__ void cp16(uint32_t daddr, const void* g) {
    asm volatile("cp.async.ca.shared.global [%0], [%1], 16;" :: "r"(daddr), "l"(g));
}
#define CP_COMMIT() asm volatile("cp.async.commit_group;" ::: "memory")
#define CP_WAIT(n)  asm volatile("cp.async.wait_group %0;" :: "n"(n) : "memory")

__device__ __forceinline__ void mma_tf32(float* c, const uint32_t* a, const uint32_t* b) {
    asm volatile(
        "mma.sync.aligned.m16n8k8.row.col.f32.tf32.tf32.f32 "
        "{%0,%1,%2,%3}, {%4,%5,%6,%7}, {%8,%9}, {%0,%1,%2,%3};"
        : "+f"(c[0]), "+f"(c[1]), "+f"(c[2]), "+f"(c[3])
        : "r"(a[0]), "r"(a[1]), "r"(a[2]), "r"(a[3]), "r"(b[0]), "r"(b[1]));
}

// ---------------- tf32 mma.sync GEMM, cp.async 2-stage, operands pre-rounded --------
#define TM_BM 128
#define TM_BN 128
#define TM_BK 32
#define TM_PAD 36
#define TM_STAGE (2 * TM_BM * TM_PAD)
#define TM_SMEM  (2 * TM_STAGE * 4)

__global__ __launch_bounds__(256, 2) void mgemm_k(
    const float* __restrict__ A, int lda,
    const float* __restrict__ Bt, int ldb, long long b_stride,
    float* __restrict__ C, int ldc,
    int rows_per_batch, int K)
{
    extern __shared__ float smf[];

    const int tid  = threadIdx.x;
    const int lane = tid & 31;
    const int wid  = tid >> 5;
    const int wm   = wid & 1;
    const int wn   = wid >> 1;
    const int gid  = lane >> 2;
    const int tig  = lane & 3;

    const int m0 = blockIdx.y * TM_BM;
    const int n0 = blockIdx.x * TM_BN;
    const int batch = m0 / rows_per_batch;
    const float* Ap = A  + (size_t)m0 * lda;
    const float* Bp = Bt + (size_t)batch * b_stride + (size_t)n0 * ldb;

    float acc[4][4][4];
    #pragma unroll
    for (int mt = 0; mt < 4; mt++)
        #pragma unroll
        for (int nt = 0; nt < 4; nt++)
            #pragma unroll
            for (int r = 0; r < 4; r++) acc[mt][nt][r] = 0.f;

    const int nk = K / TM_BK;

    #define STAGE_LOAD(S, BUF) do {                                              \
        const float* gA = Ap + (S) * TM_BK;                                       \
        const float* gB = Bp + (S) * TM_BK;                                       \
        float* sa = smf + (BUF) * TM_STAGE;                                       \
        float* sb = sa + TM_BM * TM_PAD;                                          \
        _Pragma("unroll")                                                         \
        for (int i = 0; i < 4; i++) {                                             \
            int idx = i * 256 + tid;                                              \
            int r = idx >> 3, c4 = idx & 7;                                       \
            cp16(smem_u32(sa + r * TM_PAD + c4 * 4), gA + (size_t)r * lda + c4 * 4); \
        }                                                                         \
        _Pragma("unroll")                                                         \
        for (int i = 0; i < 4; i++) {                                             \
            int idx = i * 256 + tid;                                              \
            int r = idx >> 3, c4 = idx & 7;                                       \
            cp16(smem_u32(sb + r * TM_PAD + c4 * 4), gB + (size_t)r * ldb + c4 * 4); \
        }                                                                         \
        CP_COMMIT();                                                              \
    } while (0)

    STAGE_LOAD(0, 0);

    for (int s = 0; s < nk; s++) {
        const int buf = s & 1;
        if (s + 1 < nk) { STAGE_LOAD(s + 1, buf ^ 1); CP_WAIT(1); }
        else            { CP_WAIT(0); }
        __syncthreads();

        const uint32_t* Asf = (const uint32_t*)(smf + buf * TM_STAGE);
        const uint32_t* Bsf = Asf + TM_BM * TM_PAD;

        #pragma unroll
        for (int ks = 0; ks < TM_BK / 8; ks++) {
            const int kc = ks * 8 + tig;
            uint32_t af[4][4], bf[4][2];
            #pragma unroll
            for (int mt = 0; mt < 4; mt++) {
                int row = wm * 64 + mt * 16 + gid;
                af[mt][0] = Asf[row * TM_PAD + kc];
                af[mt][1] = Asf[(row + 8) * TM_PAD + kc];
                af[mt][2] = Asf[row * TM_PAD + kc + 4];
                af[mt][3] = Asf[(row + 8) * TM_PAD + kc + 4];
            }
            #pragma unroll
            for (int nt = 0; nt < 4; nt++) {
                int nrow = wn * 32 + nt * 8 + gid;
                bf[nt][0] = Bsf[nrow * TM_PAD + kc];
                bf[nt][1] = Bsf[nrow * TM_PAD + kc + 4];
            }
            #pragma unroll
            for (int mt = 0; mt < 4; mt++)
                #pragma unroll
                for (int nt = 0; nt < 4; nt++)
                    mma_tf32(acc[mt][nt], af[mt], bf[nt]);
        }
        __syncthreads();
    }

    #pragma unroll
    for (int mt = 0; mt < 4; mt++) {
        #pragma unroll
        for (int nt = 0; nt < 4; nt++) {
            int row = m0 + wm * 64 + mt * 16 + gid;
            int col = n0 + wn * 32 + nt * 8 + tig * 2;
            *(float2*)(C + (size_t)row * ldc + col) =
                make_float2(acc[mt][nt][0], acc[mt][nt][1]);
            *(float2*)(C + (size_t)(row + 8) * ldc + col) =
                make_float2(acc[mt][nt][2], acc[mt][nt][3]);
        }
    }
}

// ---------------- cvt x -> tf32-rounded copy ----------------
__global__ void cvt_x_k(const float* __restrict__ x, float* __restrict__ xt) {
    size_t idx = (size_t)blockIdx.x * blockDim.x + threadIdx.x;
    if (idx >= ((size_t)M_TOTAL * DIM_) / 4) return;
    float4 v = ((const float4*)x)[idx];
    v.x = f2tf32f(v.x); v.y = f2tf32f(v.y);
    v.z = f2tf32f(v.z); v.w = f2tf32f(v.w);
    ((float4*)xt)[idx] = v;
}

// ---------------- transpose + round: w_qkv [K=256, N=768] -> [N][K] ----------------
__global__ void transp_k(const float* __restrict__ w, float* __restrict__ wT) {
    int idx = blockIdx.x * blockDim.x + threadIdx.x;
    if (idx >= N_QKV * DIM_) return;
    int n = idx / DIM_, k = idx % DIM_;
    wT[idx] = f2tf32f(w[(size_t)k * N_QKV + n]);
}

// ---------------- depthwise 3x3 conv, sliding y-window ----------------
// block: 8x32 pixel tile x 16 channels; thread: 4 consecutive y outputs.
__global__ __launch_bounds__(256) void dwconv_k(const float* __restrict__ in,
                                                const float* __restrict__ w,
                                                float* __restrict__ out)
{
    __shared__ float sm[10][34][16];

    const int bx = blockIdx.x;
    const int by = blockIdx.y;
    const int bz = blockIdx.z;
    const int b  = bz / 48, g48 = bz % 48;
    const int cbase = g48 * 16;
    const bool is_v = (cbase >= 2 * DIM_);

    const int tid = threadIdx.x;

    for (int i = tid; i < 10 * 34 * 4; i += 256) {
        int c4 = i & 3;
        int x  = (i >> 2) % 34;
        int y  = (i >> 2) / 34;
        int gy = by * 8 - 1 + y, gx = bx * 32 - 1 + x;
        float4 v = make_float4(0.f, 0.f, 0.f, 0.f);
        if ((unsigned)gy < (unsigned)H_ && (unsigned)gx < (unsigned)W_)
            v = *(const float4*)(in + ((size_t)(b * H_ + gy) * W_ + gx) * N_QKV + cbase + c4 * 4);
        *(float4*)&sm[y][x][c4 * 4] = v;
    }

    const int c4s = tid & 3;
    const int xo  = (tid >> 2) & 31;
    const int yg  = tid >> 7;               // 0..1, owns y outputs yg*4..yg*4+3
    float4 wv[9];
    #pragma unroll
    for (int t = 0; t < 9; t++)
        wv[t] = *(const float4*)(w + (size_t)t * N_QKV + cbase + c4s * 4);
    __syncthreads();

    float4 rA[3], rB[3], rC[3];
    #pragma unroll
    for (int dx = 0; dx < 3; dx++) {
        rA[dx] = *(const float4*)&sm[yg * 4 + 0][xo + dx][c4s * 4];
        rB[dx] = *(const float4*)&sm[yg * 4 + 1][xo + dx][c4s * 4];
    }

    #pragma unroll
    for (int i = 0; i < 4; i++) {
        #pragma unroll
        for (int dx = 0; dx < 3; dx++)
            rC[dx] = *(const float4*)&sm[yg * 4 + i + 2][xo + dx][c4s * 4];

        float4 acc = make_float4(0.f, 0.f, 0.f, 0.f);
        #pragma unroll
        for (int dx = 0; dx < 3; dx++) {
            float4 iv = rA[dx], ww = wv[dx];
            acc.x += iv.x * ww.x; acc.y += iv.y * ww.y;
            acc.z += iv.z * ww.z; acc.w += iv.w * ww.w;
        }
        #pragma unroll
        for (int dx = 0; dx < 3; dx++) {
            float4 iv = rB[dx], ww = wv[3 + dx];
            acc.x += iv.x * ww.x; acc.y += iv.y * ww.y;
            acc.z += iv.z * ww.z; acc.w += iv.w * ww.w;
        }
        #pragma unroll
        for (int dx = 0; dx < 3; dx++) {
            float4 iv = rC[dx], ww = wv[6 + dx];
            acc.x += iv.x * ww.x; acc.y += iv.y * ww.y;
            acc.z += iv.z * ww.z; acc.w += iv.w * ww.w;
        }
        if (is_v) {
            acc.x = f2tf32f(acc.x); acc.y = f2tf32f(acc.y);
            acc.z = f2tf32f(acc.z); acc.w = f2tf32f(acc.w);
        }
        int yo = yg * 4 + i;
        int gy = by * 8 + yo, gx = bx * 32 + xo;
        *(float4*)(out + ((size_t)(b * H_ + gy) * W_ + gx) * N_QKV + cbase + c4s * 4) = acc;

        #pragma unroll
        for (int dx = 0; dx < 3; dx++) { rA[dx] = rB[dx]; rB[dx] = rC[dx]; }
    }
}

// ---------------- attention partials: 2 heads per block, coalesced 128B loads ------
// grid: (b*8 head-pairs, SLICES). 256 threads = 8 s-groups x 2 heads x 16 tiles(4x4).
__global__ __launch_bounds__(256) void attn_part_k(
    const float* __restrict__ qkv2,
    const float* __restrict__ mean_q, const float* __restrict__ var_q,
    const float* __restrict__ mean_k, const float* __restrict__ var_k,
    float* __restrict__ part)
{
    const int bp = blockIdx.x;          // b*8 + p (head pair)
    const int sl = blockIdx.y;
    const int b = bp >> 3, p = bp & 7;
    __shared__ float qs[64][32];
    __shared__ float ks[64][32];
    __shared__ float red[8][2][16][16];

    const int tid  = threadIdx.x;
    const int g    = tid >> 5;              // s-group 0..7
    const int hsel = (tid >> 4) & 1;        // head within pair
    const int it   = (tid >> 2) & 3;
    const int jt   = tid & 3;
    const float* base = qkv2 + (size_t)b * HW_ * N_QKV + p * 32;

    float acc[4][4];
    #pragma unroll
    for (int a = 0; a < 4; a++)
        #pragma unroll
        for (int c = 0; c < 4; c++) acc[a][c] = 0.f;

    const int s_beg = sl * (HW_ / SLICES), s_end = s_beg + HW_ / SLICES;

    for (int s0 = s_beg; s0 < s_end; s0 += 64) {
        #pragma unroll
        for (int i = 0; i < 4; i++) {
            int idx = i * 256 + tid;            // 0..1023
            int row = idx >> 4, which = idx & 15;
            int s = s0 + row;
            const float* pr = base + (size_t)s * N_QKV;
            if (which < 8) {
                float4 v = *(const float4*)(pr + which * 4);
                float mq = mean_q[s], rvq = rsqrtf(var_q[s]);
                v.x = (v.x - mq) * rvq; v.y = (v.y - mq) * rvq;
                v.z = (v.z - mq) * rvq; v.w = (v.w - mq) * rvq;
                *(float4*)&qs[row][which * 4] = v;
            } else {
                float4 v = *(const float4*)(pr + DIM_ + (which - 8) * 4);
                float mk = mean_k[s], rvk = rsqrtf(var_k[s]);
                v.x = (v.x - mk) * rvk; v.y = (v.y - mk) * rvk;
                v.z = (v.z - mk) * rvk; v.w = (v.w - mk) * rvk;
                *(float4*)&ks[row][(which - 8) * 4] = v;
            }
        }
        __syncthreads();

        #pragma unroll
        for (int t = 0; t < 8; t++) {
            int ss = g + t * 8;
            float4 kf = *(const float4*)&ks[ss][hsel * 16 + it * 4];
            float4 qf = *(const float4*)&qs[ss][hsel * 16 + jt * 4];
            acc[0][0] += kf.x * qf.x; acc[0][1] += kf.x * qf.y;
            acc[0][2] += kf.x * qf.z; acc[0][3] += kf.x * qf.w;
            acc[1][0] += kf.y * qf.x; acc[1][1] += kf.y * qf.y;
            acc[1][2] += kf.y * qf.z; acc[1][3] += kf.y * qf.w;
            acc[2][0] += kf.z * qf.x; acc[2][1] += kf.z * qf.y;
            acc[2][2] += kf.z * qf.z; acc[2][3] += kf.z * qf.w;
            acc[3][0] += kf.w * qf.x; acc[3][1] += kf.w * qf.y;
            acc[3][2] += kf.w * qf.z; acc[3][3] += kf.w * qf.w;
        }
        __syncthreads();
    }

    #pragma unroll
    for (int a = 0; a < 4; a++)
        #pragma unroll
        for (int c = 0; c < 4; c++)
            red[g][hsel][it * 4 + a][jt * 4 + c] = acc[a][c];
    __syncthreads();

    #pragma unroll
    for (int o = 0; o < 2; o++) {
        int oi = o * 256 + tid;                 // 0..511
        int hs = oi >> 8, i2 = (oi >> 4) & 15, j2 = oi & 15;
        float r = 0.f;
        #pragma unroll
        for (int gg = 0; gg < 8; gg++) r += red[gg][hs][i2][j2];
        int bh = b * 16 + p * 2 + hs;
        part[((size_t)(sl * (B_*HEADS_) + bh)) * 256 + i2 * 16 + j2] = r;
    }
}

// ---------------- reduce slices + temperature + softmax(axis=-2) ----------------
__global__ __launch_bounds__(256) void attn_fin_k(
    const float* __restrict__ part, const float* __restrict__ temp,
    float* __restrict__ attn_out)
{
    const int bh = blockIdx.x;
    __shared__ float sm[16][16];
    const int tid = threadIdx.x;
    const int i2 = tid >> 4, j2 = tid & 15;

    float a = 0.f;
    #pragma unroll
    for (int sl = 0; sl < SLICES; sl++)
        a += part[((size_t)(sl * (B_*HEADS_) + bh)) * 256 + tid];
    a *= temp[j2];
    sm[i2][j2] = a;
    __syncthreads();

    if (tid < 16) {
        int j = tid;
        float mx = -1e30f;
        #pragma unroll
        for (int ii = 0; ii < 16; ii++) mx = fmaxf(mx, sm[ii][j]);
        float e[16]; float ssum = 0.f;
        #pragma unroll
        for (int ii = 0; ii < 16; ii++) { e[ii] = expf(sm[ii][j] - mx); ssum += e[ii]; }
        float inv = 1.f / ssum;
        #pragma unroll
        for (int ii = 0; ii < 16; ii++)
            attn_out[((size_t)bh * 16 + ii) * 16 + j] = e[ii] * inv;
    }
}

// ---------------- WfT (tf32-rounded) ----------------
__global__ __launch_bounds__(256) void wfused_k(const float* __restrict__ attn,
                                                const float* __restrict__ w_out,
                                                float* __restrict__ wfT)
{
    const int bh = blockIdx.x;
    const int b = bh >> 4, h = bh & 15;
    const int e = threadIdx.x;
    __shared__ float a[16][16];
    a[threadIdx.x >> 4][threadIdx.x & 15] = attn[(size_t)bh * 256 + threadIdx.x];
    __syncthreads();

    float w[16];
    #pragma unroll
    for (int j = 0; j < 16; j++) w[j] = w_out[(size_t)(h*16 + j) * DIM_ + e];
    #pragma unroll
    for (int d = 0; d < 16; d++) {
        float s = 0.f;
        #pragma unroll
        for (int j = 0; j < 16; j++) s += a[d][j] * w[j];
        wfT[((size_t)b * DIM_ + e) * DIM_ + (h*16 + d)] = f2tf32f(s);
    }
}

// ---------------- launch ----------------
extern "C" void kernel_launch(void* const* d_in, const int* in_sizes, int n_in,
                              void* d_out, int out_size)
{
    const float* x      = (const float*)d_in[0];
    const float* w_qkv  = (const float*)d_in[1];
    const float* w_dw   = (const float*)d_in[2];
    const float* w_out  = (const float*)d_in[3];
    const float* temp   = (const float*)d_in[4];
    const float* mean_q = (const float*)d_in[5];
    const float* var_q  = (const float*)d_in[6];
    const float* mean_k = (const float*)d_in[7];
    const float* var_k  = (const float*)d_in[8];
    float* out = (float*)d_out;

    float *xt, *qkv, *qkv2, *part, *attn, *wfT, *wqkvT;
    cudaGetSymbolAddress((void**)&xt,    g_xt);
    cudaGetSymbolAddress((void**)&qkv,   g_qkv);
    cudaGetSymbolAddress((void**)&qkv2,  g_qkv2);
    cudaGetSymbolAddress((void**)&part,  g_part);
    cudaGetSymbolAddress((void**)&attn,  g_attn);
    cudaGetSymbolAddress((void**)&wfT,   g_wfT);
    cudaGetSymbolAddress((void**)&wqkvT, g_wqkvT);

    cudaFuncSetAttribute(mgemm_k, cudaFuncAttributeMaxDynamicSharedMemorySize, TM_SMEM);

    // 0) pre-round operands to tf32
    cvt_x_k<<<(M_TOTAL * DIM_ / 4 + 255) / 256, 256>>>(x, xt);
    transp_k<<<(N_QKV * DIM_ + 255) / 256, 256>>>(w_qkv, wqkvT);

    // 1) QKV projection
    mgemm_k<<<dim3(N_QKV / TM_BN, M_TOTAL / TM_BM), 256, TM_SMEM>>>(
        xt, DIM_, wqkvT, DIM_, 0, qkv, N_QKV, M_TOTAL, DIM_);

    // 2) depthwise 3x3 conv (sliding y-window)
    dwconv_k<<<dim3(W_ / 32, H_ / 8, B_ * 48), 256>>>(qkv, w_dw, qkv2);

    // 3) channel attention partials (2 heads/block, coalesced) + reduce/softmax
    attn_part_k<<<dim3(B_ * 8, SLICES), 256>>>(qkv2, mean_q, var_q, mean_k, var_k, part);
    attn_fin_k<<<B_ * HEADS_, 256>>>(part, temp, attn);

    // 4) fold attn into output projection
    wfused_k<<<B_ * HEADS_, 256>>>(attn, w_out, wfT);

    // 5) out = v_flat @ WfT[b]^T
    mgemm_k<<<dim3(DIM_ / TM_BN, M_TOTAL / TM_BM), 256, TM_SMEM>>>(
        qkv2 + 2 * DIM_, N_QKV, wfT, DIM_, (long long)DIM_ * DIM_, out, DIM_, HW_, DIM_);
}

// round 7
// speedup vs baseline: 1.3433x; 1.3433x over previous
#include <cuda_runtime.h>
#include <math.h>
#include <stdint.h>

// ---------------- problem constants ----------------
#define B_      8
#define H_      128
#define W_      128
#define DIM_    256
#define HEADS_  16
#define DH_     16
#define HW_     (H_*W_)            // 16384
#define M_TOTAL (B_*HW_)           // 131072
#define N_QKV   (3*DIM_)           // 768
#define SLICES  8

// ---------------- scratch (no allocs -> __device__ globals) ----------------
__device__ float g_xt   [(size_t)M_TOTAL * DIM_];     // tf32-rounded x
__device__ float g_qkv  [(size_t)M_TOTAL * N_QKV];
__device__ float g_qkv2 [(size_t)M_TOTAL * N_QKV];    // v channels tf32-rounded
__device__ float g_part [SLICES * B_ * HEADS_ * DH_ * DH_];
__device__ float g_attn [B_ * HEADS_ * DH_ * DH_];
__device__ float g_wfT  [B_ * DIM_ * DIM_];           // tf32-rounded
__device__ float g_wqkvT[N_QKV * DIM_];               // tf32-rounded

// ---------------- helpers ----------------
__device__ __forceinline__ uint32_t smem_u32(const void* p) {
    uint32_t a;
    asm("{ .reg .u64 t; cvta.to.shared.u64 t, %1; cvt.u32.u64 %0, t; }" : "=r"(a) : "l"(p));
    return a;
}
__device__ __forceinline__ float f2tf32f(float f) {
    uint32_t r; asm("cvt.rna.tf32.f32 %0, %1;" : "=r"(r) : "f"(f));
    return __uint_as_float(r);
}
__device__ __forceinline__ void cp16(uint32_t daddr, const void* g) {
    asm volatile("cp.async.ca.shared.global [%0], [%1], 16;" :: "r"(daddr), "l"(g));
}
#define CP_COMMIT() asm volatile("cp.async.commit_group;" ::: "memory")
#define CP_WAIT(n)  asm volatile("cp.async.wait_group %0;" :: "n"(n) : "memory")

__device__ __forceinline__ void mma_tf32(float* c, const uint32_t* a, const uint32_t* b) {
    asm volatile(
        "mma.sync.aligned.m16n8k8.row.col.f32.tf32.tf32.f32 "
        "{%0,%1,%2,%3}, {%4,%5,%6,%7}, {%8,%9}, {%0,%1,%2,%3};"
        : "+f"(c[0]), "+f"(c[1]), "+f"(c[2]), "+f"(c[3])
        : "r"(a[0]), "r"(a[1]), "r"(a[2]), "r"(a[3]), "r"(b[0]), "r"(b[1]));
}

// ---------------- tf32 mma.sync GEMM, cp.async 2-stage, operands pre-rounded --------
#define TM_BM 128
#define TM_BN 128
#define TM_BK 32
#define TM_PAD 36
#define TM_STAGE (2 * TM_BM * TM_PAD)
#define TM_SMEM  (2 * TM_STAGE * 4)

__global__ __launch_bounds__(256, 2) void mgemm_k(
    const float* __restrict__ A, int lda,
    const float* __restrict__ Bt, int ldb, long long b_stride,
    float* __restrict__ C, int ldc,
    int rows_per_batch, int K)
{
    extern __shared__ float smf[];

    const int tid  = threadIdx.x;
    const int lane = tid & 31;
    const int wid  = tid >> 5;
    const int wm   = wid & 1;
    const int wn   = wid >> 1;
    const int gid  = lane >> 2;
    const int tig  = lane & 3;

    const int m0 = blockIdx.y * TM_BM;
    const int n0 = blockIdx.x * TM_BN;
    const int batch = m0 / rows_per_batch;
    const float* Ap = A  + (size_t)m0 * lda;
    const float* Bp = Bt + (size_t)batch * b_stride + (size_t)n0 * ldb;

    float acc[4][4][4];
    #pragma unroll
    for (int mt = 0; mt < 4; mt++)
        #pragma unroll
        for (int nt = 0; nt < 4; nt++)
            #pragma unroll
            for (int r = 0; r < 4; r++) acc[mt][nt][r] = 0.f;

    const int nk = K / TM_BK;

    #define STAGE_LOAD(S, BUF) do {                                              \
        const float* gA = Ap + (S) * TM_BK;                                       \
        const float* gB = Bp + (S) * TM_BK;                                       \
        float* sa = smf + (BUF) * TM_STAGE;                                       \
        float* sb = sa + TM_BM * TM_PAD;                                          \
        _Pragma("unroll")                                                         \
        for (int i = 0; i < 4; i++) {                                             \
            int idx = i * 256 + tid;                                              \
            int r = idx >> 3, c4 = idx & 7;                                       \
            cp16(smem_u32(sa + r * TM_PAD + c4 * 4), gA + (size_t)r * lda + c4 * 4); \
        }                                                                         \
        _Pragma("unroll")                                                         \
        for (int i = 0; i < 4; i++) {                                             \
            int idx = i * 256 + tid;                                              \
            int r = idx >> 3, c4 = idx & 7;                                       \
            cp16(smem_u32(sb + r * TM_PAD + c4 * 4), gB + (size_t)r * ldb + c4 * 4); \
        }                                                                         \
        CP_COMMIT();                                                              \
    } while (0)

    STAGE_LOAD(0, 0);

    for (int s = 0; s < nk; s++) {
        const int buf = s & 1;
        if (s + 1 < nk) { STAGE_LOAD(s + 1, buf ^ 1); CP_WAIT(1); }
        else            { CP_WAIT(0); }
        __syncthreads();

        const uint32_t* Asf = (const uint32_t*)(smf + buf * TM_STAGE);
        const uint32_t* Bsf = Asf + TM_BM * TM_PAD;

        #pragma unroll
        for (int ks = 0; ks < TM_BK / 8; ks++) {
            const int kc = ks * 8 + tig;
            uint32_t af[4][4], bf[4][2];
            #pragma unroll
            for (int mt = 0; mt < 4; mt++) {
                int row = wm * 64 + mt * 16 + gid;
                af[mt][0] = Asf[row * TM_PAD + kc];
                af[mt][1] = Asf[(row + 8) * TM_PAD + kc];
                af[mt][2] = Asf[row * TM_PAD + kc + 4];
                af[mt][3] = Asf[(row + 8) * TM_PAD + kc + 4];
            }
            #pragma unroll
            for (int nt = 0; nt < 4; nt++) {
                int nrow = wn * 32 + nt * 8 + gid;
                bf[nt][0] = Bsf[nrow * TM_PAD + kc];
                bf[nt][1] = Bsf[nrow * TM_PAD + kc + 4];
            }
            #pragma unroll
            for (int mt = 0; mt < 4; mt++)
                #pragma unroll
                for (int nt = 0; nt < 4; nt++)
                    mma_tf32(acc[mt][nt], af[mt], bf[nt]);
        }
        __syncthreads();
    }

    #pragma unroll
    for (int mt = 0; mt < 4; mt++) {
        #pragma unroll
        for (int nt = 0; nt < 4; nt++) {
            int row = m0 + wm * 64 + mt * 16 + gid;
            int col = n0 + wn * 32 + nt * 8 + tig * 2;
            *(float2*)(C + (size_t)row * ldc + col) =
                make_float2(acc[mt][nt][0], acc[mt][nt][1]);
            *(float2*)(C + (size_t)(row + 8) * ldc + col) =
                make_float2(acc[mt][nt][2], acc[mt][nt][3]);
        }
    }
}

// ---------------- cvt x -> tf32-rounded copy ----------------
__global__ void cvt_x_k(const float* __restrict__ x, float* __restrict__ xt) {
    size_t idx = (size_t)blockIdx.x * blockDim.x + threadIdx.x;
    if (idx >= ((size_t)M_TOTAL * DIM_) / 4) return;
    float4 v = ((const float4*)x)[idx];
    v.x = f2tf32f(v.x); v.y = f2tf32f(v.y);
    v.z = f2tf32f(v.z); v.w = f2tf32f(v.w);
    ((float4*)xt)[idx] = v;
}

// ---------------- transpose + round: w_qkv [K=256, N=768] -> [N][K] ----------------
__global__ void transp_k(const float* __restrict__ w, float* __restrict__ wT) {
    int idx = blockIdx.x * blockDim.x + threadIdx.x;
    if (idx >= N_QKV * DIM_) return;
    int n = idx / DIM_, k = idx % DIM_;
    wT[idx] = f2tf32f(w[(size_t)k * N_QKV + n]);
}

// ---------------- depthwise 3x3 conv, float2 sliding y-window ----------------
// block: 8x32 pixel tile x 16 channels; thread = (channel-pair, x), 8 y outputs.
__global__ __launch_bounds__(256) void dwconv_k(const float* __restrict__ in,
                                                const float* __restrict__ w,
                                                float* __restrict__ out)
{
    __shared__ float sm[10][34][16];

    const int bx = blockIdx.x;
    const int by = blockIdx.y;
    const int bz = blockIdx.z;
    const int b  = bz / 48, g48 = bz % 48;
    const int cbase = g48 * 16;
    const bool is_v = (cbase >= 2 * DIM_);

    const int tid = threadIdx.x;

    // load 10x34 halo tile (float4 granularity, same as R5)
    for (int i = tid; i < 10 * 34 * 4; i += 256) {
        int c4 = i & 3;
        int x  = (i >> 2) % 34;
        int y  = (i >> 2) / 34;
        int gy = by * 8 - 1 + y, gx = bx * 32 - 1 + x;
        float4 v = make_float4(0.f, 0.f, 0.f, 0.f);
        if ((unsigned)gy < (unsigned)H_ && (unsigned)gx < (unsigned)W_)
            v = *(const float4*)(in + ((size_t)(b * H_ + gy) * W_ + gx) * N_QKV + cbase + c4 * 4);
        *(float4*)&sm[y][x][c4 * 4] = v;
    }

    const int c2s = tid & 7;            // channel pair 0..7
    const int xo  = tid >> 3;           // 0..31

    float2 wv[9];
    #pragma unroll
    for (int t = 0; t < 9; t++)
        wv[t] = *(const float2*)(w + (size_t)t * N_QKV + cbase + c2s * 2);
    __syncthreads();

    float2 rA[3], rB[3], rC[3];
    #pragma unroll
    for (int dx = 0; dx < 3; dx++) {
        rA[dx] = *(const float2*)&sm[0][xo + dx][c2s * 2];
        rB[dx] = *(const float2*)&sm[1][xo + dx][c2s * 2];
    }

    #pragma unroll
    for (int yo = 0; yo < 8; yo++) {
        #pragma unroll
        for (int dx = 0; dx < 3; dx++)
            rC[dx] = *(const float2*)&sm[yo + 2][xo + dx][c2s * 2];

        float2 acc = make_float2(0.f, 0.f);
        #pragma unroll
        for (int dx = 0; dx < 3; dx++) {
            acc.x += rA[dx].x * wv[dx].x;     acc.y += rA[dx].y * wv[dx].y;
        }
        #pragma unroll
        for (int dx = 0; dx < 3; dx++) {
            acc.x += rB[dx].x * wv[3 + dx].x; acc.y += rB[dx].y * wv[3 + dx].y;
        }
        #pragma unroll
        for (int dx = 0; dx < 3; dx++) {
            acc.x += rC[dx].x * wv[6 + dx].x; acc.y += rC[dx].y * wv[6 + dx].y;
        }
        if (is_v) { acc.x = f2tf32f(acc.x); acc.y = f2tf32f(acc.y); }

        int gy = by * 8 + yo, gx = bx * 32 + xo;
        *(float2*)(out + ((size_t)(b * H_ + gy) * W_ + gx) * N_QKV + cbase + c2s * 2) = acc;

        #pragma unroll
        for (int dx = 0; dx < 3; dx++) { rA[dx] = rB[dx]; rB[dx] = rC[dx]; }
    }
}

// ---------------- attention partials: 4x4 register tiles (R5 version) ----------------
__global__ __launch_bounds__(256) void attn_part_k(
    const float* __restrict__ qkv2,
    const float* __restrict__ mean_q, const float* __restrict__ var_q,
    const float* __restrict__ mean_k, const float* __restrict__ var_k,
    float* __restrict__ part)
{
    const int bh = blockIdx.x;
    const int sl = blockIdx.y;
    const int b = bh >> 4, h = bh & 15;
    __shared__ float qs[64][16];
    __shared__ float ks[64][16];
    __shared__ float red[16][16][16];

    const int tid  = threadIdx.x;
    const int tile = tid & 15;
    const int g    = tid >> 4;
    const int it   = tile >> 2, jt = tile & 3;
    const int ls   = tid >> 2;
    const int li   = (tid & 3) * 4;
    const float* base = qkv2 + (size_t)b * HW_ * N_QKV + h * DH_;

    float acc[4][4];
    #pragma unroll
    for (int a = 0; a < 4; a++)
        #pragma unroll
        for (int c = 0; c < 4; c++) acc[a][c] = 0.f;

    const int s_beg = sl * (HW_ / SLICES), s_end = s_beg + HW_ / SLICES;

    for (int s0 = s_beg; s0 < s_end; s0 += 64) {
        int s = s0 + ls;
        float mq = mean_q[s], rvq = rsqrtf(var_q[s]);
        float mk = mean_k[s], rvk = rsqrtf(var_k[s]);
        const float* p = base + (size_t)s * N_QKV + li;
        float4 qv = *(const float4*)(p);
        float4 kv = *(const float4*)(p + DIM_);
        qs[ls][li+0] = (qv.x - mq) * rvq;
        qs[ls][li+1] = (qv.y - mq) * rvq;
        qs[ls][li+2] = (qv.z - mq) * rvq;
        qs[ls][li+3] = (qv.w - mq) * rvq;
        ks[ls][li+0] = (kv.x - mk) * rvk;
        ks[ls][li+1] = (kv.y - mk) * rvk;
        ks[ls][li+2] = (kv.z - mk) * rvk;
        ks[ls][li+3] = (kv.w - mk) * rvk;
        __syncthreads();

        #pragma unroll
        for (int t = 0; t < 4; t++) {
            int ss = g + t * 16;
            float4 kf = *(const float4*)&ks[ss][it * 4];
            float4 qf = *(const float4*)&qs[ss][jt * 4];
            acc[0][0] += kf.x * qf.x; acc[0][1] += kf.x * qf.y;
            acc[0][2] += kf.x * qf.z; acc[0][3] += kf.x * qf.w;
            acc[1][0] += kf.y * qf.x; acc[1][1] += kf.y * qf.y;
            acc[1][2] += kf.y * qf.z; acc[1][3] += kf.y * qf.w;
            acc[2][0] += kf.z * qf.x; acc[2][1] += kf.z * qf.y;
            acc[2][2] += kf.z * qf.z; acc[2][3] += kf.z * qf.w;
            acc[3][0] += kf.w * qf.x; acc[3][1] += kf.w * qf.y;
            acc[3][2] += kf.w * qf.z; acc[3][3] += kf.w * qf.w;
        }
        __syncthreads();
    }

    #pragma unroll
    for (int a = 0; a < 4; a++)
        #pragma unroll
        for (int c = 0; c < 4; c++)
            red[g][it * 4 + a][jt * 4 + c] = acc[a][c];
    __syncthreads();

    const int i2 = tid >> 4, j2 = tid & 15;
    float r = 0.f;
    #pragma unroll
    for (int gg = 0; gg < 16; gg++) r += red[gg][i2][j2];
    part[((size_t)(sl * (B_*HEADS_) + bh)) * 256 + i2 * 16 + j2] = r;
}

// ---------------- reduce slices + temperature + softmax(axis=-2) ----------------
__global__ __launch_bounds__(256) void attn_fin_k(
    const float* __restrict__ part, const float* __restrict__ temp,
    float* __restrict__ attn_out)
{
    const int bh = blockIdx.x;
    __shared__ float sm[16][16];
    const int tid = threadIdx.x;
    const int i2 = tid >> 4, j2 = tid & 15;

    float a = 0.f;
    #pragma unroll
    for (int sl = 0; sl < SLICES; sl++)
        a += part[((size_t)(sl * (B_*HEADS_) + bh)) * 256 + tid];
    a *= temp[j2];
    sm[i2][j2] = a;
    __syncthreads();

    if (tid < 16) {
        int j = tid;
        float mx = -1e30f;
        #pragma unroll
        for (int ii = 0; ii < 16; ii++) mx = fmaxf(mx, sm[ii][j]);
        float e[16]; float ssum = 0.f;
        #pragma unroll
        for (int ii = 0; ii < 16; ii++) { e[ii] = expf(sm[ii][j] - mx); ssum += e[ii]; }
        float inv = 1.f / ssum;
        #pragma unroll
        for (int ii = 0; ii < 16; ii++)
            attn_out[((size_t)bh * 16 + ii) * 16 + j] = e[ii] * inv;
    }
}

// ---------------- WfT (tf32-rounded) ----------------
__global__ __launch_bounds__(256) void wfused_k(const float* __restrict__ attn,
                                                const float* __restrict__ w_out,
                                                float* __restrict__ wfT)
{
    const int bh = blockIdx.x;
    const int b = bh >> 4, h = bh & 15;
    const int e = threadIdx.x;
    __shared__ float a[16][16];
    a[threadIdx.x >> 4][threadIdx.x & 15] = attn[(size_t)bh * 256 + threadIdx.x];
    __syncthreads();

    float w[16];
    #pragma unroll
    for (int j = 0; j < 16; j++) w[j] = w_out[(size_t)(h*16 + j) * DIM_ + e];
    #pragma unroll
    for (int d = 0; d < 16; d++) {
        float s = 0.f;
        #pragma unroll
        for (int j = 0; j < 16; j++) s += a[d][j] * w[j];
        wfT[((size_t)b * DIM_ + e) * DIM_ + (h*16 + d)] = f2tf32f(s);
    }
}

// ---------------- launch ----------------
extern "C" void kernel_launch(void* const* d_in, const int* in_sizes, int n_in,
                              void* d_out, int out_size)
{
    const float* x      = (const float*)d_in[0];
    const float* w_qkv  = (const float*)d_in[1];
    const float* w_dw   = (const float*)d_in[2];
    const float* w_out  = (const float*)d_in[3];
    const float* temp   = (const float*)d_in[4];
    const float* mean_q = (const float*)d_in[5];
    const float* var_q  = (const float*)d_in[6];
    const float* mean_k = (const float*)d_in[7];
    const float* var_k  = (const float*)d_in[8];
    float* out = (float*)d_out;

    float *xt, *qkv, *qkv2, *part, *attn, *wfT, *wqkvT;
    cudaGetSymbolAddress((void**)&xt,    g_xt);
    cudaGetSymbolAddress((void**)&qkv,   g_qkv);
    cudaGetSymbolAddress((void**)&qkv2,  g_qkv2);
    cudaGetSymbolAddress((void**)&part,  g_part);
    cudaGetSymbolAddress((void**)&attn,  g_attn);
    cudaGetSymbolAddress((void**)&wfT,   g_wfT);
    cudaGetSymbolAddress((void**)&wqkvT, g_wqkvT);

    cudaFuncSetAttribute(mgemm_k, cudaFuncAttributeMaxDynamicSharedMemorySize, TM_SMEM);

    // 0) pre-round operands to tf32
    cvt_x_k<<<(M_TOTAL * DIM_ / 4 + 255) / 256, 256>>>(x, xt);
    transp_k<<<(N_QKV * DIM_ + 255) / 256, 256>>>(w_qkv, wqkvT);

    // 1) QKV projection
    mgemm_k<<<dim3(N_QKV / TM_BN, M_TOTAL / TM_BM), 256, TM_SMEM>>>(
        xt, DIM_, wqkvT, DIM_, 0, qkv, N_QKV, M_TOTAL, DIM_);

    // 2) depthwise 3x3 conv (float2 sliding y-window)
    dwconv_k<<<dim3(W_ / 32, H_ / 8, B_ * 48), 256>>>(qkv, w_dw, qkv2);

    // 3) channel attention partials + reduce/softmax
    attn_part_k<<<dim3(B_ * HEADS_, SLICES), 256>>>(qkv2, mean_q, var_q, mean_k, var_k, part);
    attn_fin_k<<<B_ * HEADS_, 256>>>(part, temp, attn);

    // 4) fold attn into output projection
    wfused_k<<<B_ * HEADS_, 256>>>(attn, w_out, wfT);

    // 5) out = v_flat @ WfT[b]^T
    mgemm_k<<<dim3(DIM_ / TM_BN, M_TOTAL / TM_BM), 256, TM_SMEM>>>(
        qkv2 + 2 * DIM_, N_QKV, wfT, DIM_, (long long)DIM_ * DIM_, out, DIM_, HW_, DIM_);
}

// round 8
// speedup vs baseline: 1.6436x; 1.2235x over previous
#include <cuda_runtime.h>
#include <cuda_fp16.h>
#include <math.h>
#include <stdint.h>

// ---------------- problem constants ----------------
#define B_      8
#define H_      128
#define W_      128
#define DIM_    256
#define HEADS_  16
#define DH_     16
#define HW_     (H_*W_)            // 16384
#define M_TOTAL (B_*HW_)           // 131072
#define N_QKV   (3*DIM_)           // 768
#define SLICES  8

// ---------------- scratch (no allocs -> __device__ globals) ----------------
__device__ __half g_xh   [(size_t)M_TOTAL * DIM_];    // fp16 x
__device__ float  g_qkv  [(size_t)M_TOTAL * N_QKV];   // pre-conv qkv (fp32)
__device__ float  g_qkv2 [(size_t)M_TOTAL * N_QKV];   // post-conv q,k (fp32; v region unused)
__device__ __half g_vh   [(size_t)M_TOTAL * DIM_];    // post-conv v (fp16)
__device__ float  g_part [SLICES * B_ * HEADS_ * DH_ * DH_];
__device__ float  g_attn [B_ * HEADS_ * DH_ * DH_];
__device__ __half g_wfTh [B_ * DIM_ * DIM_];          // fused W^T per batch (fp16)
__device__ __half g_wqkvTh[N_QKV * DIM_];             // w_qkv^T (fp16)

// ---------------- helpers ----------------
__device__ __forceinline__ uint32_t smem_u32(const void* p) {
    uint32_t a;
    asm("{ .reg .u64 t; cvta.to.shared.u64 t, %1; cvt.u32.u64 %0, t; }" : "=r"(a) : "l"(p));
    return a;
}
__device__ __forceinline__ void cp16(uint32_t daddr, const void* g) {
    asm volatile("cp.async.ca.shared.global [%0], [%1], 16;" :: "r"(daddr), "l"(g));
}
#define CP_COMMIT() asm volatile("cp.async.commit_group;" ::: "memory")
#define CP_WAIT(n)  asm volatile("cp.async.wait_group %0;" :: "n"(n) : "memory")

__device__ __forceinline__ void mma_f16(float* c, const uint32_t* a, const uint32_t* b) {
    asm volatile(
        "mma.sync.aligned.m16n8k16.row.col.f32.f16.f16.f32 "
        "{%0,%1,%2,%3}, {%4,%5,%6,%7}, {%8,%9}, {%0,%1,%2,%3};"
        : "+f"(c[0]), "+f"(c[1]), "+f"(c[2]), "+f"(c[3])
        : "r"(a[0]), "r"(a[1]), "r"(a[2]), "r"(a[3]), "r"(b[0]), "r"(b[1]));
}

// ---------------- fp16 mma.sync GEMM, cp.async 2-stage ----------------
// C[M,N](fp32) = A[M,K](fp16) @ Bt[N,K](fp16)^T. CTA 128x128, k-tile 32,
// 8 warps (2m x 4n), warp 64x32, m16n8k16.
#define TM_BM 128
#define TM_BN 128
#define TM_BK 32
#define TM_PADH 40                          // halves per row (80B, conflict-free)
#define TM_TILEH (TM_BM * TM_PADH)          // halves per operand tile
#define TM_STAGEH (2 * TM_TILEH)            // A + B

__global__ __launch_bounds__(256, 2) void mgemm_k(
    const __half* __restrict__ A, int lda,
    const __half* __restrict__ Bt, int ldb, long long b_stride,
    float* __restrict__ C, int ldc,
    int rows_per_batch, int K)
{
    __shared__ __half smh[2 * TM_STAGEH];   // 40960 B

    const int tid  = threadIdx.x;
    const int lane = tid & 31;
    const int wid  = tid >> 5;
    const int wm   = wid & 1;
    const int wn   = wid >> 1;
    const int gid  = lane >> 2;
    const int tig  = lane & 3;

    const int m0 = blockIdx.y * TM_BM;
    const int n0 = blockIdx.x * TM_BN;
    const int batch = m0 / rows_per_batch;
    const __half* Ap = A  + (size_t)m0 * lda;
    const __half* Bp = Bt + (size_t)batch * b_stride + (size_t)n0 * ldb;

    float acc[4][4][4];
    #pragma unroll
    for (int mt = 0; mt < 4; mt++)
        #pragma unroll
        for (int nt = 0; nt < 4; nt++)
            #pragma unroll
            for (int r = 0; r < 4; r++) acc[mt][nt][r] = 0.f;

    const int nk = K / TM_BK;

    // per stage: A tile 128x32 halves + B tile 128x32 halves; 2 cp16 each per thread
    #define STAGE_LOAD(S, BUF) do {                                               \
        const __half* gA = Ap + (S) * TM_BK;                                       \
        const __half* gB = Bp + (S) * TM_BK;                                       \
        __half* sa = smh + (BUF) * TM_STAGEH;                                      \
        __half* sb = sa + TM_TILEH;                                                \
        _Pragma("unroll")                                                          \
        for (int i = 0; i < 2; i++) {                                              \
            int idx = i * 256 + tid;                                               \
            int r = idx >> 2, c8 = idx & 3;                                        \
            cp16(smem_u32(sa + r * TM_PADH + c8 * 8), gA + (size_t)r * lda + c8 * 8); \
        }                                                                          \
        _Pragma("unroll")                                                          \
        for (int i = 0; i < 2; i++) {                                              \
            int idx = i * 256 + tid;                                               \
            int r = idx >> 2, c8 = idx & 3;                                        \
            cp16(smem_u32(sb + r * TM_PADH + c8 * 8), gB + (size_t)r * ldb + c8 * 8); \
        }                                                                          \
        CP_COMMIT();                                                               \
    } while (0)

    STAGE_LOAD(0, 0);

    for (int s = 0; s < nk; s++) {
        const int buf = s & 1;
        if (s + 1 < nk) { STAGE_LOAD(s + 1, buf ^ 1); CP_WAIT(1); }
        else            { CP_WAIT(0); }
        __syncthreads();

        // u32 view: one u32 = half2 at even k; row stride = 20 u32
        const uint32_t* As32 = (const uint32_t*)(smh + buf * TM_STAGEH);
        const uint32_t* Bs32 = As32 + TM_TILEH / 2;

        #pragma unroll
        for (int ks = 0; ks < 2; ks++) {            // 2 x k16 per k-tile 32
            const int kb = ks * 8 + tig;            // u32 index in row
            uint32_t af[4][4], bf[4][2];
            #pragma unroll
            for (int mt = 0; mt < 4; mt++) {
                int row = wm * 64 + mt * 16 + gid;
                af[mt][0] = As32[row * 20 + kb];
                af[mt][1] = As32[(row + 8) * 20 + kb];
                af[mt][2] = As32[row * 20 + kb + 4];
                af[mt][3] = As32[(row + 8) * 20 + kb + 4];
            }
            #pragma unroll
            for (int nt = 0; nt < 4; nt++) {
                int nrow = wn * 32 + nt * 8 + gid;
                bf[nt][0] = Bs32[nrow * 20 + kb];
                bf[nt][1] = Bs32[nrow * 20 + kb + 4];
            }
            #pragma unroll
            for (int mt = 0; mt < 4; mt++)
                #pragma unroll
                for (int nt = 0; nt < 4; nt++)
                    mma_f16(acc[mt][nt], af[mt], bf[nt]);
        }
        __syncthreads();
    }

    #pragma unroll
    for (int mt = 0; mt < 4; mt++) {
        #pragma unroll
        for (int nt = 0; nt < 4; nt++) {
            int row = m0 + wm * 64 + mt * 16 + gid;
            int col = n0 + wn * 32 + nt * 8 + tig * 2;
            *(float2*)(C + (size_t)row * ldc + col) =
                make_float2(acc[mt][nt][0], acc[mt][nt][1]);
            *(float2*)(C + (size_t)(row + 8) * ldc + col) =
                make_float2(acc[mt][nt][2], acc[mt][nt][3]);
        }
    }
}

// ---------------- cvt x -> fp16 copy ----------------
__global__ void cvt_x_k(const float* __restrict__ x, __half* __restrict__ xh) {
    size_t idx = (size_t)blockIdx.x * blockDim.x + threadIdx.x;
    if (idx >= ((size_t)M_TOTAL * DIM_) / 4) return;
    float4 v = ((const float4*)x)[idx];
    __half2 h0 = __floats2half2_rn(v.x, v.y);
    __half2 h1 = __floats2half2_rn(v.z, v.w);
    ((uint2*)xh)[idx] = make_uint2(*(uint32_t*)&h0, *(uint32_t*)&h1);
}

// ---------------- transpose + cvt: w_qkv [K=256, N=768] -> half [N][K] -------------
__global__ void transp_k(const float* __restrict__ w, __half* __restrict__ wT) {
    int idx = blockIdx.x * blockDim.x + threadIdx.x;
    if (idx >= N_QKV * DIM_) return;
    int n = idx / DIM_, k = idx % DIM_;
    wT[idx] = __float2half_rn(w[(size_t)k * N_QKV + n]);
}

// ---------------- depthwise 3x3 conv, float2 sliding y-window ----------------
// q,k channels -> qkv2 (fp32); v channels -> g_vh (fp16).
__global__ __launch_bounds__(256) void dwconv_k(const float* __restrict__ in,
                                                const float* __restrict__ w,
                                                float* __restrict__ out,
                                                __half* __restrict__ vh)
{
    __shared__ float sm[10][34][16];

    const int bx = blockIdx.x;
    const int by = blockIdx.y;
    const int bz = blockIdx.z;
    const int b  = bz / 48, g48 = bz % 48;
    const int cbase = g48 * 16;
    const bool is_v = (cbase >= 2 * DIM_);

    const int tid = threadIdx.x;

    for (int i = tid; i < 10 * 34 * 4; i += 256) {
        int c4 = i & 3;
        int x  = (i >> 2) % 34;
        int y  = (i >> 2) / 34;
        int gy = by * 8 - 1 + y, gx = bx * 32 - 1 + x;
        float4 v = make_float4(0.f, 0.f, 0.f, 0.f);
        if ((unsigned)gy < (unsigned)H_ && (unsigned)gx < (unsigned)W_)
            v = *(const float4*)(in + ((size_t)(b * H_ + gy) * W_ + gx) * N_QKV + cbase + c4 * 4);
        *(float4*)&sm[y][x][c4 * 4] = v;
    }

    const int c2s = tid & 7;
    const int xo  = tid >> 3;

    float2 wv[9];
    #pragma unroll
    for (int t = 0; t < 9; t++)
        wv[t] = *(const float2*)(w + (size_t)t * N_QKV + cbase + c2s * 2);
    __syncthreads();

    float2 rA[3], rB[3], rC[3];
    #pragma unroll
    for (int dx = 0; dx < 3; dx++) {
        rA[dx] = *(const float2*)&sm[0][xo + dx][c2s * 2];
        rB[dx] = *(const float2*)&sm[1][xo + dx][c2s * 2];
    }

    #pragma unroll
    for (int yo = 0; yo < 8; yo++) {
        #pragma unroll
        for (int dx = 0; dx < 3; dx++)
            rC[dx] = *(const float2*)&sm[yo + 2][xo + dx][c2s * 2];

        float2 acc = make_float2(0.f, 0.f);
        #pragma unroll
        for (int dx = 0; dx < 3; dx++) {
            acc.x += rA[dx].x * wv[dx].x;     acc.y += rA[dx].y * wv[dx].y;
        }
        #pragma unroll
        for (int dx = 0; dx < 3; dx++) {
            acc.x += rB[dx].x * wv[3 + dx].x; acc.y += rB[dx].y * wv[3 + dx].y;
        }
        #pragma unroll
        for (int dx = 0; dx < 3; dx++) {
            acc.x += rC[dx].x * wv[6 + dx].x; acc.y += rC[dx].y * wv[6 + dx].y;
        }

        int gy = by * 8 + yo, gx = bx * 32 + xo;
        if (is_v) {
            __half2 hv = __floats2half2_rn(acc.x, acc.y);
            *(__half2*)(vh + ((size_t)(b * H_ + gy) * W_ + gx) * DIM_ + (cbase - 2 * DIM_) + c2s * 2) = hv;
        } else {
            *(float2*)(out + ((size_t)(b * H_ + gy) * W_ + gx) * N_QKV + cbase + c2s * 2) = acc;
        }

        #pragma unroll
        for (int dx = 0; dx < 3; dx++) { rA[dx] = rB[dx]; rB[dx] = rC[dx]; }
    }
}

// ---------------- attention partials: 4x4 register tiles ----------------
__global__ __launch_bounds__(256) void attn_part_k(
    const float* __restrict__ qkv2,
    const float* __restrict__ mean_q, const float* __restrict__ var_q,
    const float* __restrict__ mean_k, const float* __restrict__ var_k,
    float* __restrict__ part)
{
    const int bh = blockIdx.x;
    const int sl = blockIdx.y;
    const int b = bh >> 4, h = bh & 15;
    __shared__ float qs[64][16];
    __shared__ float ks[64][16];
    __shared__ float red[16][16][16];

    const int tid  = threadIdx.x;
    const int tile = tid & 15;
    const int g    = tid >> 4;
    const int it   = tile >> 2, jt = tile & 3;
    const int ls   = tid >> 2;
    const int li   = (tid & 3) * 4;
    const float* base = qkv2 + (size_t)b * HW_ * N_QKV + h * DH_;

    float acc[4][4];
    #pragma unroll
    for (int a = 0; a < 4; a++)
        #pragma unroll
        for (int c = 0; c < 4; c++) acc[a][c] = 0.f;

    const int s_beg = sl * (HW_ / SLICES), s_end = s_beg + HW_ / SLICES;

    for (int s0 = s_beg; s0 < s_end; s0 += 64) {
        int s = s0 + ls;
        float mq = mean_q[s], rvq = rsqrtf(var_q[s]);
        float mk = mean_k[s], rvk = rsqrtf(var_k[s]);
        const float* p = base + (size_t)s * N_QKV + li;
        float4 qv = *(const float4*)(p);
        float4 kv = *(const float4*)(p + DIM_);
        qs[ls][li+0] = (qv.x - mq) * rvq;
        qs[ls][li+1] = (qv.y - mq) * rvq;
        qs[ls][li+2] = (qv.z - mq) * rvq;
        qs[ls][li+3] = (qv.w - mq) * rvq;
        ks[ls][li+0] = (kv.x - mk) * rvk;
        ks[ls][li+1] = (kv.y - mk) * rvk;
        ks[ls][li+2] = (kv.z - mk) * rvk;
        ks[ls][li+3] = (kv.w - mk) * rvk;
        __syncthreads();

        #pragma unroll
        for (int t = 0; t < 4; t++) {
            int ss = g + t * 16;
            float4 kf = *(const float4*)&ks[ss][it * 4];
            float4 qf = *(const float4*)&qs[ss][jt * 4];
            acc[0][0] += kf.x * qf.x; acc[0][1] += kf.x * qf.y;
            acc[0][2] += kf.x * qf.z; acc[0][3] += kf.x * qf.w;
            acc[1][0] += kf.y * qf.x; acc[1][1] += kf.y * qf.y;
            acc[1][2] += kf.y * qf.z; acc[1][3] += kf.y * qf.w;
            acc[2][0] += kf.z * qf.x; acc[2][1] += kf.z * qf.y;
            acc[2][2] += kf.z * qf.z; acc[2][3] += kf.z * qf.w;
            acc[3][0] += kf.w * qf.x; acc[3][1] += kf.w * qf.y;
            acc[3][2] += kf.w * qf.z; acc[3][3] += kf.w * qf.w;
        }
        __syncthreads();
    }

    #pragma unroll
    for (int a = 0; a < 4; a++)
        #pragma unroll
        for (int c = 0; c < 4; c++)
            red[g][it * 4 + a][jt * 4 + c] = acc[a][c];
    __syncthreads();

    const int i2 = tid >> 4, j2 = tid & 15;
    float r = 0.f;
    #pragma unroll
    for (int gg = 0; gg < 16; gg++) r += red[gg][i2][j2];
    part[((size_t)(sl * (B_*HEADS_) + bh)) * 256 + i2 * 16 + j2] = r;
}

// ---------------- reduce slices + temperature + softmax(axis=-2) ----------------
__global__ __launch_bounds__(256) void attn_fin_k(
    const float* __restrict__ part, const float* __restrict__ temp,
    float* __restrict__ attn_out)
{
    const int bh = blockIdx.x;
    __shared__ float sm[16][16];
    const int tid = threadIdx.x;
    const int i2 = tid >> 4, j2 = tid & 15;

    float a = 0.f;
    #pragma unroll
    for (int sl = 0; sl < SLICES; sl++)
        a += part[((size_t)(sl * (B_*HEADS_) + bh)) * 256 + tid];
    a *= temp[j2];
    sm[i2][j2] = a;
    __syncthreads();

    if (tid < 16) {
        int j = tid;
        float mx = -1e30f;
        #pragma unroll
        for (int ii = 0; ii < 16; ii++) mx = fmaxf(mx, sm[ii][j]);
        float e[16]; float ssum = 0.f;
        #pragma unroll
        for (int ii = 0; ii < 16; ii++) { e[ii] = expf(sm[ii][j] - mx); ssum += e[ii]; }
        float inv = 1.f / ssum;
        #pragma unroll
        for (int ii = 0; ii < 16; ii++)
            attn_out[((size_t)bh * 16 + ii) * 16 + j] = e[ii] * inv;
    }
}

// ---------------- WfT (fp16) ----------------
__global__ __launch_bounds__(256) void wfused_k(const float* __restrict__ attn,
                                                const float* __restrict__ w_out,
                                                __half* __restrict__ wfTh)
{
    const int bh = blockIdx.x;
    const int b = bh >> 4, h = bh & 15;
    const int e = threadIdx.x;
    __shared__ float a[16][16];
    a[threadIdx.x >> 4][threadIdx.x & 15] = attn[(size_t)bh * 256 + threadIdx.x];
    __syncthreads();

    float w[16];
    #pragma unroll
    for (int j = 0; j < 16; j++) w[j] = w_out[(size_t)(h*16 + j) * DIM_ + e];
    #pragma unroll
    for (int d = 0; d < 16; d++) {
        float s = 0.f;
        #pragma unroll
        for (int j = 0; j < 16; j++) s += a[d][j] * w[j];
        wfTh[((size_t)b * DIM_ + e) * DIM_ + (h*16 + d)] = __float2half_rn(s);
    }
}

// ---------------- launch ----------------
extern "C" void kernel_launch(void* const* d_in, const int* in_sizes, int n_in,
                              void* d_out, int out_size)
{
    const float* x      = (const float*)d_in[0];
    const float* w_qkv  = (const float*)d_in[1];
    const float* w_dw   = (const float*)d_in[2];
    const float* w_out  = (const float*)d_in[3];
    const float* temp   = (const float*)d_in[4];
    const float* mean_q = (const float*)d_in[5];
    const float* var_q  = (const float*)d_in[6];
    const float* mean_k = (const float*)d_in[7];
    const float* var_k  = (const float*)d_in[8];
    float* out = (float*)d_out;

    __half *xh, *vh, *wfTh, *wqkvTh;
    float *qkv, *qkv2, *part, *attn;
    cudaGetSymbolAddress((void**)&xh,     g_xh);
    cudaGetSymbolAddress((void**)&qkv,    g_qkv);
    cudaGetSymbolAddress((void**)&qkv2,   g_qkv2);
    cudaGetSymbolAddress((void**)&vh,     g_vh);
    cudaGetSymbolAddress((void**)&part,   g_part);
    cudaGetSymbolAddress((void**)&attn,   g_attn);
    cudaGetSymbolAddress((void**)&wfTh,   g_wfTh);
    cudaGetSymbolAddress((void**)&wqkvTh, g_wqkvTh);

    // 0) convert operands to fp16
    cvt_x_k<<<(M_TOTAL * DIM_ / 4 + 255) / 256, 256>>>(x, xh);
    transp_k<<<(N_QKV * DIM_ + 255) / 256, 256>>>(w_qkv, wqkvTh);

    // 1) QKV projection: fp16 mma (fp32 accumulate/output)
    mgemm_k<<<dim3(N_QKV / TM_BN, M_TOTAL / TM_BM), 256>>>(
        xh, DIM_, wqkvTh, DIM_, 0, qkv, N_QKV, M_TOTAL, DIM_);

    // 2) depthwise 3x3 conv: q,k -> fp32, v -> fp16
    dwconv_k<<<dim3(W_ / 32, H_ / 8, B_ * 48), 256>>>(qkv, w_dw, qkv2, vh);

    // 3) channel attention partials + reduce/softmax (fp32)
    attn_part_k<<<dim3(B_ * HEADS_, SLICES), 256>>>(qkv2, mean_q, var_q, mean_k, var_k, part);
    attn_fin_k<<<B_ * HEADS_, 256>>>(part, temp, attn);

    // 4) fold attn into output projection (fp16)
    wfused_k<<<B_ * HEADS_, 256>>>(attn, w_out, wfTh);

    // 5) out = v @ WfT[b]^T : fp16 mma
    mgemm_k<<<dim3(DIM_ / TM_BN, M_TOTAL / TM_BM), 256>>>(
        vh, DIM_, wfTh, DIM_, (long long)DIM_ * DIM_, out, DIM_, HW_, DIM_);
}